// round 15
// baseline (speedup 1.0000x reference)
#include <cuda_runtime.h>
#include <cuda_fp16.h>

#define N_NODES 100000
#define N_EDGES 1600000
#define HMW 32            // concatenated mu(16) | logstd(16)
#define OUTC 16

#define FB 1184           // 148 SMs x 8 blocks (exactly resident: 2048 thr/SM)
#define FT 256
#define FTOT (FB * FT)    // 303104 threads
#define EPT 6             // ceil(N_EDGES / FTOT)

// ---------------- scratch (device globals; zero at module load) ------------------
// deg/acc0 zeroed at tail of k_scatter1 (for the NEXT launch); acc1h zeroed in
// k_edges phase A (before scatter1 writes it). Module-load zero covers launch 1.
__device__ float  g_deg  [N_NODES];         // in-degree count (dst)
__device__ float  g_acc0 [N_NODES * 2];     // layer-1 aggregation of dis*x
__device__ float  g_dis  [N_NODES];         // rsqrt(1+deg), written by k_hidden
__device__ __half g_gvech[N_NODES * HMW];   // gvec fp16 (gather payload + REDG operand)
__device__ float  g_gself[N_NODES * HMW];   // gvec f32 exact (self-loop term)
__device__ __half g_acc1h[N_NODES * HMW];   // fp16 neighbor accumulator (REDG f16x2)
__device__ int    g_src32[N_EDGES];         // compacted src (int64 input only)
__device__ int    g_dst32[N_EDGES];         // compacted dst (int64 input only)
__device__ int    g_is64;                   // dtype flag (written by k_edges)
__device__ unsigned long long g_bar;        // monotonic barrier ticket (never reset)

#define DEG_ZT (N_NODES * HMW / 8)          // acc1h uint4s = 400000

// ---------------- vectorized L2 reductions (sm_90+) -----------------------------
__device__ __forceinline__ void red_add_v2(float* addr, float a, float b) {
    asm volatile("red.global.add.v2.f32 [%0], {%1, %2};"
                 :: "l"(addr), "f"(a), "f"(b) : "memory");
}
// 8 packed halves (4 x f16x2) in one 16B reduction lane
__device__ __forceinline__ void red_add_v4h2(__half* addr, uint4 w) {
    asm volatile("red.global.add.noftz.v4.f16x2 [%0], {%1, %2, %3, %4};"
                 :: "l"(addr), "r"(w.x), "r"(w.y), "r"(w.z), "r"(w.w) : "memory");
}

// ---------------- fused degree + layer-1 scatter (persistent, 1 grid barrier) ----
// Phase A: per-block dtype detect; count degrees (+ compaction iff int64); hold
// this thread's <=6 edges in registers; zero acc1h. Barrier. Phase B: scatter
// dis[src]*x[src] into acc0 using the register-held edges (no index re-read).
// Monotonic ticket barrier: graph-replay safe, no resets.
__global__ void __launch_bounds__(FT, 8) k_edges(const void* ei,
                                                 const float* __restrict__ x) {
    __shared__ unsigned s_or[FT];
    int t = threadIdx.x;
    s_or[t] = ((const unsigned*)ei)[2 * t + 1];
    __syncthreads();
    for (int s = 128; s > 0; s >>= 1) {
        if (t < s) s_or[t] |= s_or[t + s];
        __syncthreads();
    }
    int is64 = (s_or[0] == 0u) ? 1 : 0;   // int64 idx < 100000 -> high words all 0
    int gtid = blockIdx.x * FT + t;
    if (gtid == 0) g_is64 = is64;

    int es[EPT], ed[EPT];
    #pragma unroll
    for (int i = 0; i < EPT; i++) {
        int e = gtid + i * FTOT;
        if (e < N_EDGES) {
            int s_, d_;
            if (is64) {
                const long long* p = (const long long*)ei;
                s_ = (int)p[e];
                d_ = (int)p[N_EDGES + e];
                g_src32[e] = s_;          // compaction for k_scatter1
                g_dst32[e] = d_;
            } else {
                const int* p = (const int*)ei;
                s_ = p[e];
                d_ = p[N_EDGES + e];
            }
            es[i] = s_; ed[i] = d_;
            atomicAdd(&g_deg[d_], 1.0f);
        } else {
            es[i] = -1; ed[i] = 0;
        }
    }
    for (int z = gtid; z < DEG_ZT; z += FTOT)      // zero fp16 accumulator
        ((uint4*)g_acc1h)[z] = make_uint4(0u, 0u, 0u, 0u);

    // ---- grid barrier (all FB blocks resident by construction) ----
    __syncthreads();
    if (t == 0) {
        __threadfence();
        unsigned long long tk = atomicAdd(&g_bar, 1ULL);
        unsigned long long target = (tk / FB + 1ULL) * (unsigned long long)FB;
        unsigned long long v;
        do {
            asm volatile("ld.acquire.gpu.b64 %0, [%1];"
                         : "=l"(v) : "l"(&g_bar) : "memory");
        } while (v < target);
    }
    __syncthreads();

    // ---- phase B: layer-1 scatter from register-held edges ----
    #pragma unroll
    for (int i = 0; i < EPT; i++) {
        if (es[i] >= 0) {
            float ds = rsqrtf(1.0f + g_deg[es[i]]);
            float2 xv = ((const float2*)x)[es[i]];
            red_add_v2(&g_acc0[2 * ed[i]], ds * xv.x, ds * xv.y);
        }
    }
}

__device__ __forceinline__ void load_edge(const void* ei, int is64, int e,
                                          int& src, int& dst) {
    if (is64) { src = g_src32[e]; dst = g_dst32[e]; }
    else {
        const int* p = (const int*)ei;
        src = p[e];
        dst = p[N_EDGES + e];
    }
}

// ---------------- dense: h = relu(aggX @ W1 + b1); g = dis * (h @ [Wmu|Wls]) ----
// 4 threads/node (8 outputs each) x 4 nodes/thread (R6/R8-proven shape).
// Writes gvec fp16 (gather/REDG payload), exact f32 self term to g_gself, and
// part-0 lanes persist g_dis for the epilogue.
__global__ void __launch_bounds__(256) k_hidden(
        const float* __restrict__ x, const float* __restrict__ W1,
        const float* __restrict__ b1,
        const float* __restrict__ Wmu, const float* __restrict__ Wls) {
    __shared__ float4 sW4[64][8];   // [k][j/4] of concatenated [Wmu|Wls]
    __shared__ float4 sWb[64];      // (W1[0][k], W1[1][k], b1[k], 0)

    int t = threadIdx.x;
    for (int i = t; i < 512; i += 256) {
        int k = i >> 3, q = i & 7;
        sW4[k][q] = (q < 4) ? ((const float4*)Wmu)[k * 4 + q]
                            : ((const float4*)Wls)[k * 4 + (q - 4)];
    }
    if (t < 64) sWb[t] = make_float4(W1[t], W1[64 + t], b1[t], 0.0f);
    __syncthreads();

    int part = t & 3;               // which 8 of the 32 outputs
    int u    = t >> 2;              // 0..63
    int base = blockIdx.x * 256;

    float a0[4], a1[4], dd[4];
    #pragma unroll
    for (int i = 0; i < 4; i++) {
        int n = base + u + 64 * i;
        int nc = (n < N_NODES) ? n : 0;
        float d = rsqrtf(1.0f + g_deg[nc]);
        float2 xv = ((const float2*)x)[nc];
        float2 av = ((const float2*)g_acc0)[nc];
        a0[i] = d * av.x + d * d * xv.x;
        a1[i] = d * av.y + d * d * xv.y;
        dd[i] = d;
    }

    float acc[4][8];
    #pragma unroll
    for (int i = 0; i < 4; i++)
        #pragma unroll
        for (int j = 0; j < 8; j++) acc[i][j] = 0.0f;

    int q0 = part * 2;
    #pragma unroll 4
    for (int k = 0; k < 64; k++) {
        float4 wb = sWb[k];
        float4 wA = sW4[k][q0];
        float4 wB = sW4[k][q0 + 1];
        #pragma unroll
        for (int i = 0; i < 4; i++) {
            float hk = fmaxf(0.0f, fmaf(a0[i], wb.x, fmaf(a1[i], wb.y, wb.z)));
            acc[i][0] = fmaf(hk, wA.x, acc[i][0]);
            acc[i][1] = fmaf(hk, wA.y, acc[i][1]);
            acc[i][2] = fmaf(hk, wA.z, acc[i][2]);
            acc[i][3] = fmaf(hk, wA.w, acc[i][3]);
            acc[i][4] = fmaf(hk, wB.x, acc[i][4]);
            acc[i][5] = fmaf(hk, wB.y, acc[i][5]);
            acc[i][6] = fmaf(hk, wB.z, acc[i][6]);
            acc[i][7] = fmaf(hk, wB.w, acc[i][7]);
        }
    }

    #pragma unroll
    for (int i = 0; i < 4; i++) {
        int n = base + u + 64 * i;
        if (n < N_NODES) {
            float4 vA = make_float4(dd[i] * acc[i][0], dd[i] * acc[i][1],
                                    dd[i] * acc[i][2], dd[i] * acc[i][3]);
            float4 vB = make_float4(dd[i] * acc[i][4], dd[i] * acc[i][5],
                                    dd[i] * acc[i][6], dd[i] * acc[i][7]);
            float4* sout = (float4*)(g_gself + n * HMW + part * 8);
            sout[0] = vA;                  // exact f32 self-loop term
            sout[1] = vB;
            __half2 h0 = __float22half2_rn(make_float2(vA.x, vA.y));
            __half2 h1 = __float22half2_rn(make_float2(vA.z, vA.w));
            __half2 h2 = __float22half2_rn(make_float2(vB.x, vB.y));
            __half2 h3 = __float22half2_rn(make_float2(vB.z, vB.w));
            uint4 pk;
            pk.x = *(unsigned*)&h0; pk.y = *(unsigned*)&h1;
            pk.z = *(unsigned*)&h2; pk.w = *(unsigned*)&h3;
            *(uint4*)(g_gvech + n * HMW + part * 8) = pk;
            if (part == 0) g_dis[n] = dd[i];   // persist for epilogue
        }
    }
}

// ---------------- layer-2 scatter (fp16 packed REDG) + accumulator re-zeroing ----
// Edge range: 4 threads/edge; each gathers one uint4 (8 halves of gvech[src])
// and fires ONE red.v4.f16x2 (8 halves/lane) -> 6.4M REDG lanes.
// Tail range: zero deg + acc0 for the NEXT launch.
#define S1_EDGE_T (N_EDGES * 4)
#define S1_ZD     (N_NODES / 4)          // deg float4s   (25000)
#define S1_ZA     (N_NODES * 2 / 4)      // acc0 float4s  (50000)
#define S1_TOTAL  (S1_EDGE_T + S1_ZD + S1_ZA)
__global__ void k_scatter1(const void* ei) {
    int tid = blockIdx.x * 256 + threadIdx.x;
    if (tid < S1_EDGE_T) {
        int e = tid >> 2, q = tid & 3;
        int src, dst;
        load_edge(ei, g_is64, e, src, dst);
        uint4 w = ((const uint4*)g_gvech)[src * 4 + q];     // 8 halves
        red_add_v4h2(g_acc1h + dst * HMW + q * 8, w);
    } else {
        int z = tid - S1_EDGE_T;
        const float4 zero = make_float4(0.f, 0.f, 0.f, 0.f);
        if (z < S1_ZD)                ((float4*)g_deg )[z] = zero;
        else if (z < S1_ZD + S1_ZA)   ((float4*)g_acc0)[z - S1_ZD] = zero;
    }
}

// ---------------- epilogue: out = dis*(acc1h + gself) + bias --------------------
__global__ void k_out(const float* __restrict__ bmu, const float* __restrict__ bls,
                      float* __restrict__ out) {
    int tid = blockIdx.x * 256 + threadIdx.x;       // over N_NODES * 8 quads
    if (tid >= N_NODES * 8) return;
    int n = tid >> 3, q = tid & 7;
    float d = g_dis[n];
    uint2 hw = ((const uint2*)g_acc1h)[tid];        // 4 halves (neighbor sum)
    float2 f0 = __half22float2(*(__half2*)&hw.x);
    float2 f1 = __half22float2(*(__half2*)&hw.y);
    float4 s = ((const float4*)g_gself)[tid];       // exact self term
    float4 b = (q < 4) ? ((const float4*)bmu)[q] : ((const float4*)bls)[q - 4];
    float4 v = make_float4(fmaf(d, f0.x + s.x, b.x), fmaf(d, f0.y + s.y, b.y),
                           fmaf(d, f1.x + s.z, b.z), fmaf(d, f1.y + s.w, b.w));
    float* dst = (q < 4) ? out + n * OUTC + q * 4
                         : out + N_NODES * OUTC + n * OUTC + (q - 4) * 4;
    *(float4*)dst = v;
}

extern "C" void kernel_launch(void* const* d_in, const int* in_sizes, int n_in,
                              void* d_out, int out_size) {
    const float* x    = (const float*)d_in[0];
    const void*  ei   = d_in[1];                 // int32 or int64, detected on device
    const float* W1   = (const float*)d_in[2];
    const float* b1   = (const float*)d_in[3];
    const float* Wmu  = (const float*)d_in[4];
    const float* bmu  = (const float*)d_in[5];
    const float* Wls  = (const float*)d_in[6];
    const float* bls  = (const float*)d_in[7];
    float* out = (float*)d_out;

    const int HB  = (N_NODES + 255) / 256;                // 391
    const int OB  = (N_NODES * 8 + 255) / 256;            // 3125
    const int S1B = (S1_TOTAL + 255) / 256;               // 25293

    k_edges<<<FB, FT>>>(ei, x);
    k_hidden<<<HB, 256>>>(x, W1, b1, Wmu, Wls);
    k_scatter1<<<S1B, 256>>>(ei);
    k_out<<<OB, 256>>>(bmu, bls, out);
}

// round 16
// speedup vs baseline: 1.0744x; 1.0744x over previous
#include <cuda_runtime.h>
#include <cuda_fp16.h>

#define N_NODES 100000
#define N_EDGES 1600000
#define HMW 32            // concatenated mu(16) | logstd(16)
#define OUTC 16

// ---------------- scratch (device globals; zero at module load) ------------------
// deg/acc0 are accumulators: zeroed at tail of k_scatter1 for the NEXT launch
// (module-load zero covers launch 1). gvech/acc1h/dis are fully overwritten by
// k_hidden each launch (acc1h's overwrite IS its initialization: fp16 self term).
__device__ float  g_deg  [N_NODES];         // in-degree count (dst)
__device__ float  g_acc0 [N_NODES * 2];     // layer-1 aggregation of dis*x
__device__ float  g_dis  [N_NODES];         // rsqrt(1+deg), written by k_hidden
__device__ __half g_gvech[N_NODES * HMW];   // gvec fp16 (gather payload + REDG operand)
__device__ __half g_acc1h[N_NODES * HMW];   // fp16 accumulator, seeded = fp16 self term
__device__ int    g_src32[N_EDGES];         // compacted src (int64 input only)
__device__ int    g_dst32[N_EDGES];         // compacted dst (int64 input only)
__device__ int    g_is64;                   // dtype flag (written by k_deg)

// ---------------- vectorized L2 reductions (sm_90+) -----------------------------
__device__ __forceinline__ void red_add_v2(float* addr, float a, float b) {
    asm volatile("red.global.add.v2.f32 [%0], {%1, %2};"
                 :: "l"(addr), "f"(a), "f"(b) : "memory");
}
// 8 packed halves (4 x f16x2) in one 16B reduction lane
__device__ __forceinline__ void red_add_v4h2(__half* addr, uint4 w) {
    asm volatile("red.global.add.noftz.v4.f16x2 [%0], {%1, %2, %3, %4};"
                 :: "l"(addr), "r"(w.x), "r"(w.y), "r"(w.z), "r"(w.w) : "memory");
}

// ---------------- degree + per-block dtype detect (+ compaction iff int64) -------
// Detect: 256 odd words sampled per block. int64 indices < 100000 have zero high
// words; int32 data puts edge values there (P(all 256 == 0) astronomically small).
__global__ void k_deg(const void* ei) {
    __shared__ unsigned s_or[256];
    int t = threadIdx.x;
    s_or[t] = ((const unsigned*)ei)[2 * t + 1];
    __syncthreads();
    for (int s = 128; s > 0; s >>= 1) {
        if (t < s) s_or[t] |= s_or[t + s];
        __syncthreads();
    }
    int is64 = (s_or[0] == 0u) ? 1 : 0;
    if (blockIdx.x == 0 && t == 0) g_is64 = is64;

    int e = blockIdx.x * 256 + t;
    if (e >= N_EDGES) return;
    if (is64) {
        const long long* p = (const long long*)ei;
        int src = (int)p[e];
        int dst = (int)p[N_EDGES + e];
        g_src32[e] = src;
        g_dst32[e] = dst;
        atomicAdd(&g_deg[dst], 1.0f);
    } else {
        atomicAdd(&g_deg[((const int*)ei)[N_EDGES + e]], 1.0f);
    }
}

__device__ __forceinline__ void load_edge(const void* ei, int is64, int e,
                                          int& src, int& dst) {
    if (is64) { src = g_src32[e]; dst = g_dst32[e]; }
    else {
        const int* p = (const int*)ei;
        src = p[e];
        dst = p[N_EDGES + e];
    }
}

// ---------------- layer-1 scatter: acc0[dst] += dis[src] * x[src]  (2 feats) ----
__global__ void k_scatter0(const void* ei, const float* __restrict__ x) {
    int e = blockIdx.x * 256 + threadIdx.x;
    if (e >= N_EDGES) return;
    int src, dst;
    load_edge(ei, g_is64, e, src, dst);
    float ds = rsqrtf(1.0f + g_deg[src]);
    float2 xv = ((const float2*)x)[src];
    red_add_v2(&g_acc0[2 * dst], ds * xv.x, ds * xv.y);
}

// ---------------- dense: h = relu(aggX @ W1 + b1); g = dis * (h @ [Wmu|Wls]) ----
// 4 threads/node (8 outputs each) x 4 nodes/thread (R6/R8-proven shape).
// Writes gvec fp16 to BOTH gvech (scatter payload) and acc1h (self-loop seed =
// the accumulator's initialization; no zeroing pass, no f32 sidecar).
// part-0 lanes persist g_dis for the epilogue.
__global__ void __launch_bounds__(256) k_hidden(
        const float* __restrict__ x, const float* __restrict__ W1,
        const float* __restrict__ b1,
        const float* __restrict__ Wmu, const float* __restrict__ Wls) {
    __shared__ float4 sW4[64][8];   // [k][j/4] of concatenated [Wmu|Wls]
    __shared__ float4 sWb[64];      // (W1[0][k], W1[1][k], b1[k], 0)

    int t = threadIdx.x;
    for (int i = t; i < 512; i += 256) {
        int k = i >> 3, q = i & 7;
        sW4[k][q] = (q < 4) ? ((const float4*)Wmu)[k * 4 + q]
                            : ((const float4*)Wls)[k * 4 + (q - 4)];
    }
    if (t < 64) sWb[t] = make_float4(W1[t], W1[64 + t], b1[t], 0.0f);
    __syncthreads();

    int part = t & 3;               // which 8 of the 32 outputs
    int u    = t >> 2;              // 0..63
    int base = blockIdx.x * 256;

    float a0[4], a1[4], dd[4];
    #pragma unroll
    for (int i = 0; i < 4; i++) {
        int n = base + u + 64 * i;
        int nc = (n < N_NODES) ? n : 0;
        float d = rsqrtf(1.0f + g_deg[nc]);
        float2 xv = ((const float2*)x)[nc];
        float2 av = ((const float2*)g_acc0)[nc];
        a0[i] = d * av.x + d * d * xv.x;
        a1[i] = d * av.y + d * d * xv.y;
        dd[i] = d;
    }

    float acc[4][8];
    #pragma unroll
    for (int i = 0; i < 4; i++)
        #pragma unroll
        for (int j = 0; j < 8; j++) acc[i][j] = 0.0f;

    int q0 = part * 2;
    #pragma unroll 4
    for (int k = 0; k < 64; k++) {
        float4 wb = sWb[k];
        float4 wA = sW4[k][q0];
        float4 wB = sW4[k][q0 + 1];
        #pragma unroll
        for (int i = 0; i < 4; i++) {
            float hk = fmaxf(0.0f, fmaf(a0[i], wb.x, fmaf(a1[i], wb.y, wb.z)));
            acc[i][0] = fmaf(hk, wA.x, acc[i][0]);
            acc[i][1] = fmaf(hk, wA.y, acc[i][1]);
            acc[i][2] = fmaf(hk, wA.z, acc[i][2]);
            acc[i][3] = fmaf(hk, wA.w, acc[i][3]);
            acc[i][4] = fmaf(hk, wB.x, acc[i][4]);
            acc[i][5] = fmaf(hk, wB.y, acc[i][5]);
            acc[i][6] = fmaf(hk, wB.z, acc[i][6]);
            acc[i][7] = fmaf(hk, wB.w, acc[i][7]);
        }
    }

    #pragma unroll
    for (int i = 0; i < 4; i++) {
        int n = base + u + 64 * i;
        if (n < N_NODES) {
            __half2 h0 = __float22half2_rn(make_float2(dd[i] * acc[i][0], dd[i] * acc[i][1]));
            __half2 h1 = __float22half2_rn(make_float2(dd[i] * acc[i][2], dd[i] * acc[i][3]));
            __half2 h2 = __float22half2_rn(make_float2(dd[i] * acc[i][4], dd[i] * acc[i][5]));
            __half2 h3 = __float22half2_rn(make_float2(dd[i] * acc[i][6], dd[i] * acc[i][7]));
            uint4 pk;
            pk.x = *(unsigned*)&h0; pk.y = *(unsigned*)&h1;
            pk.z = *(unsigned*)&h2; pk.w = *(unsigned*)&h3;
            *(uint4*)(g_gvech + n * HMW + part * 8) = pk;   // scatter payload
            *(uint4*)(g_acc1h + n * HMW + part * 8) = pk;   // accumulator seed
            if (part == 0) g_dis[n] = dd[i];                // persist for epilogue
        }
    }
}

// ---------------- layer-2 scatter (fp16 packed REDG) + accumulator re-zeroing ----
// Edge range: 4 threads/edge; each gathers one uint4 (8 halves of gvech[src])
// and fires ONE red.v4.f16x2 (8 halves/lane) -> 6.4M REDG lanes.
// Tail range: zero deg + acc0 for the NEXT launch.
#define S1_EDGE_T (N_EDGES * 4)
#define S1_ZD     (N_NODES / 4)          // deg float4s   (25000)
#define S1_ZA     (N_NODES * 2 / 4)      // acc0 float4s  (50000)
#define S1_TOTAL  (S1_EDGE_T + S1_ZD + S1_ZA)
__global__ void k_scatter1(const void* ei) {
    int tid = blockIdx.x * 256 + threadIdx.x;
    if (tid < S1_EDGE_T) {
        int e = tid >> 2, q = tid & 3;
        int src, dst;
        load_edge(ei, g_is64, e, src, dst);
        uint4 w = ((const uint4*)g_gvech)[src * 4 + q];     // 8 halves
        red_add_v4h2(g_acc1h + dst * HMW + q * 8, w);
    } else {
        int z = tid - S1_EDGE_T;
        const float4 zero = make_float4(0.f, 0.f, 0.f, 0.f);
        if (z < S1_ZD)                ((float4*)g_deg )[z] = zero;
        else if (z < S1_ZD + S1_ZA)   ((float4*)g_acc0)[z - S1_ZD] = zero;
    }
}

// ---------------- epilogue: out = dis*acc1h + bias; split mu / logstd -----------
__global__ void k_out(const float* __restrict__ bmu, const float* __restrict__ bls,
                      float* __restrict__ out) {
    int tid = blockIdx.x * 256 + threadIdx.x;       // over N_NODES * 8 quads
    if (tid >= N_NODES * 8) return;
    int n = tid >> 3, q = tid & 7;
    float d = g_dis[n];
    uint2 hw = ((const uint2*)g_acc1h)[tid];        // 4 halves (self + neighbors)
    float2 f0 = __half22float2(*(__half2*)&hw.x);
    float2 f1 = __half22float2(*(__half2*)&hw.y);
    float4 b = (q < 4) ? ((const float4*)bmu)[q] : ((const float4*)bls)[q - 4];
    float4 v = make_float4(fmaf(d, f0.x, b.x), fmaf(d, f0.y, b.y),
                           fmaf(d, f1.x, b.z), fmaf(d, f1.y, b.w));
    float* dst = (q < 4) ? out + n * OUTC + q * 4
                         : out + N_NODES * OUTC + n * OUTC + (q - 4) * 4;
    *(float4*)dst = v;
}

extern "C" void kernel_launch(void* const* d_in, const int* in_sizes, int n_in,
                              void* d_out, int out_size) {
    const float* x    = (const float*)d_in[0];
    const void*  ei   = d_in[1];                 // int32 or int64, detected on device
    const float* W1   = (const float*)d_in[2];
    const float* b1   = (const float*)d_in[3];
    const float* Wmu  = (const float*)d_in[4];
    const float* bmu  = (const float*)d_in[5];
    const float* Wls  = (const float*)d_in[6];
    const float* bls  = (const float*)d_in[7];
    float* out = (float*)d_out;

    const int EB  = (N_EDGES + 255) / 256;                // 6250
    const int HB  = (N_NODES + 255) / 256;                // 391
    const int OB  = (N_NODES * 8 + 255) / 256;            // 3125
    const int S1B = (S1_TOTAL + 255) / 256;               // 25293

    k_deg<<<EB, 256>>>(ei);
    k_scatter0<<<EB, 256>>>(ei, x);
    k_hidden<<<HB, 256>>>(x, W1, b1, Wmu, Wls);
    k_scatter1<<<S1B, 256>>>(ei);
    k_out<<<OB, 256>>>(bmu, bls, out);
}